// round 4
// baseline (speedup 1.0000x reference)
#include <cuda_runtime.h>
#include <cuda_bf16.h>
#include <cstddef>

// Problem constants (fixed by the reference setup)
#define BB    16
#define TRED  512
#define CC    512
#define TT    32        // t-rows per block
#define NTH   512       // threads per block
#define C4    (CC / 4)  // float4 per row = 128

// Fused kernel:
//  - per-block: recompute inclusive prefix sum of durations[b] in smem (cheap,
//    512 int32 from L2 + 9-step Hillis-Steele)
//  - warp 0: binary-search segment index for the block's TT t-rows, write mask
//  - all threads: float4 gather pooled_x[b, seg, :] -> out[b, t, :] (or zeros)
__global__ __launch_bounds__(NTH)
void upsample_kernel(const float* __restrict__ px,
                     const int*   __restrict__ dur,
                     const int*   __restrict__ target_T,
                     float*       __restrict__ out,
                     int max_len, int write_mask)
{
    __shared__ int csum[TRED];
    __shared__ int seg_s[TT];
    __shared__ int valid_s[TT];

    const int b   = blockIdx.y;
    const int tid = threadIdx.x;
    const int t0  = blockIdx.x * TT;

    // ---- load durations + inclusive scan (Hillis-Steele, 512 lanes) ----
    csum[tid] = dur[b * TRED + tid];
    __syncthreads();
    #pragma unroll
    for (int off = 1; off < TRED; off <<= 1) {
        int add = (tid >= off) ? csum[tid - off] : 0;
        __syncthreads();
        csum[tid] += add;
        __syncthreads();
    }

    const int total    = csum[TRED - 1];
    const int curr_len = min(total, target_T[b]);   // == total by construction, but honor ref

    // ---- one warp: segment lookup + mask write for this block's t-rows ----
    if (tid < TT) {
        const int t     = t0 + tid;
        const int valid = (t < max_len) && (t < curr_len);
        int seg = 0;
        if (valid) {
            // first i with csum[i] > t  (searchsorted right)
            int lo = 0, hi = TRED;
            while (lo < hi) {
                int mid = (lo + hi) >> 1;
                if (csum[mid] > t) hi = mid; else lo = mid + 1;
            }
            seg = min(lo, TRED - 1);
        }
        seg_s[tid]   = seg;
        valid_s[tid] = valid;
        if (write_mask && t < max_len) {
            float* mask = out + (size_t)BB * max_len * CC;
            mask[(size_t)b * max_len + t] = valid ? 0.0f : 1.0f;
        }
    }
    __syncthreads();

    // ---- streamed gather: 128 threads per t-row, 4 rows per wave ----
    const int row = tid / C4;     // 0..3
    const int c4  = tid % C4;     // 0..127
    const float4* px4  = (const float4*)px;
    float4*       out4 = (float4*)out;

    #pragma unroll
    for (int r = row; r < TT; r += NTH / C4) {
        const int t = t0 + r;
        if (t >= max_len) continue;
        float4 v;
        if (valid_s[r]) {
            v = px4[((size_t)b * TRED + seg_s[r]) * C4 + c4];
        } else {
            v = make_float4(0.0f, 0.0f, 0.0f, 0.0f);
        }
        out4[((size_t)b * max_len + t) * C4 + c4] = v;
    }
}

extern "C" void kernel_launch(void* const* d_in, const int* in_sizes, int n_in,
                              void* d_out, int out_size)
{
    const float* px  = (const float*)d_in[0];   // pooled_x  (B, T_RED, C) f32
    const int*   dur = (const int*)  d_in[1];   // durations (B, T_RED)   i32
    const int*   tgt = (const int*)  d_in[2];   // target_T  (B,)         i32

    // Recover max_len from out_size. Expected layout: [x (B*max_len*C)] ++ [mask (B*max_len)].
    int max_len, write_mask;
    if (out_size % (BB * (CC + 1)) == 0) {
        max_len    = out_size / (BB * (CC + 1));
        write_mask = 1;
    } else {
        max_len    = out_size / (BB * CC);   // fallback: x-only output
        write_mask = 0;
    }

    dim3 grid((max_len + TT - 1) / TT, BB);
    upsample_kernel<<<grid, NTH>>>(px, dur, tgt, (float*)d_out, max_len, write_mask);
}